// round 8
// baseline (speedup 1.0000x reference)
#include <cuda_runtime.h>
#include <math.h>

#define B_     2048
#define S_     96
#define F_     32
#define H_     256
#define O_     6
#define LA_    32
#define WARM_  96
#define STEPS_ 128
#define MB_    14
#define PAIRS_ 7
#define NTH_   512
#define NBLK_  147          // ceil(2048 / 14)
#define KTOT_  (F_ + H_)    // 288: rows 0..31 = x_t, rows 32..287 = h
#define HSTRIDE_ 20         // floats per state row (14 data + 6 pad), 16B-aligned
#define CK_    16           // k-slices per weight chunk
#define NCHUNK_ (KTOT_ / CK_)   // 18; chunks 0..8 = k[0,144), 9..17 = k[144,288)
#define SPLIT_CHUNK_ 8      // snapshot after this chunk to replicate proven fp order
#define NBUF_  3
#define CHUNK_FLOATS_ (CK_ * H_ * 4)      // 16384 floats = 64 KB
#define CHUNK_BYTES_  (CHUNK_FLOATS_ * 4)

typedef unsigned long long ull;

// Static device scratch (no allocation allowed).
__device__ float4 g_W[KTOT_ * H_];   // [k][jh] -> (i,f,g,o)
__device__ float4 g_bias[H_];        // combined bias (i,f,g,o)

// ---- packed fp32x2 helpers ----
__device__ __forceinline__ ull ffma2(ull a, ull b, ull c) {
    ull d;
    asm("fma.rn.f32x2 %0, %1, %2, %3;" : "=l"(d) : "l"(a), "l"(b), "l"(c));
    return d;
}
__device__ __forceinline__ ull add2(ull a, ull b) {
    ull d;
    asm("add.rn.f32x2 %0, %1, %2;" : "=l"(d) : "l"(a), "l"(b));
    return d;
}
__device__ __forceinline__ ull splat2(float x) {
    ull d; unsigned u = __float_as_uint(x);
    asm("mov.b64 %0, {%1, %1};" : "=l"(d) : "r"(u));
    return d;
}
__device__ __forceinline__ float2 unpk(ull v) {
    unsigned lo, hi;
    asm("mov.b64 {%0, %1}, %2;" : "=r"(lo), "=r"(hi) : "l"(v));
    return make_float2(__uint_as_float(lo), __uint_as_float(hi));
}
__device__ __forceinline__ ull pk(float a, float b) {
    ull d;
    asm("mov.b64 %0, {%1, %2};" : "=l"(d) : "r"(__float_as_uint(a)), "r"(__float_as_uint(b)));
    return d;
}
// ACCURATE activations — identical to R6 (proven at rel_err 1.6e-7).
__device__ __forceinline__ float sigf(float x) { return 1.0f / (1.0f + expf(-x)); }
__device__ __forceinline__ float tanh_acc(float x) {   // branchless, libm-grade
    float ax = fabsf(x);
    float e  = expf(-2.0f * ax);
    float t  = (1.0f - e) / (1.0f + e);
    return copysignf(t, x);
}

// ---- cp.async helpers ----
__device__ __forceinline__ void cp16(unsigned dst, const void* src) {
    asm volatile("cp.async.cg.shared.global [%0], [%1], 16;\n" :: "r"(dst), "l"(src));
}
#define CP_COMMIT() asm volatile("cp.async.commit_group;\n" ::: "memory")
#define CP_WAIT1()  asm volatile("cp.async.wait_group 1;\n" ::: "memory")

// One-time weight interleave: combined (x|h) k range, 4-gate float4, bias fold.
__global__ void pack_kernel(const float* __restrict__ Wih, const float* __restrict__ Whh,
                            const float* __restrict__ bih, const float* __restrict__ bhh) {
    int idx = blockIdx.x * blockDim.x + threadIdx.x;
    if (idx >= KTOT_ * H_) return;
    int k  = idx >> 8;
    int jh = idx & 255;
    float4 v;
    if (k < F_) {
        v.x = Wih[(0 * H_ + jh) * F_ + k];
        v.y = Wih[(1 * H_ + jh) * F_ + k];
        v.z = Wih[(2 * H_ + jh) * F_ + k];
        v.w = Wih[(3 * H_ + jh) * F_ + k];
    } else {
        int kk = k - F_;
        v.x = Whh[(0 * H_ + jh) * H_ + kk];
        v.y = Whh[(1 * H_ + jh) * H_ + kk];
        v.z = Whh[(2 * H_ + jh) * H_ + kk];
        v.w = Whh[(3 * H_ + jh) * H_ + kk];
    }
    g_W[idx] = v;
    if (k == 0) {
        float4 b;
        b.x = bih[0 * H_ + jh] + bhh[0 * H_ + jh];
        b.y = bih[1 * H_ + jh] + bhh[1 * H_ + jh];
        b.z = bih[2 * H_ + jh] + bhh[2 * H_ + jh];
        b.w = bih[3 * H_ + jh] + bhh[3 * H_ + jh];
        g_bias[jh] = b;
    }
}

// Issue one weight chunk (16 k-rows x 256 jh float4) via cp.async. All 512 threads.
__device__ __forceinline__ void issue_chunk(unsigned buf_u32, int m, int tid) {
    int hi  = tid >> 8;          // 0 or 1: row parity
    int col = tid & 255;
    const float4* src = g_W + (size_t)(m * CK_ + hi) * H_ + col;
    unsigned dst = buf_u32 + (unsigned)(((hi * H_) + col) << 4);
#pragma unroll
    for (int r = 0; r < 8; r++) {
        cp16(dst, src);
        src += 2 * H_;
        dst += 2 * H_ * 16;
    }
    CP_COMMIT();
}

// GEMM over one chunk: NP batch pairs (at float offset ROFF in the state row),
// 4 gates. Weight from smem buffer, state broadcast from S.
template <int NP, int ROFF>
__device__ __forceinline__ void chunk_gemm(const float4* __restrict__ wbuf, int jh,
                                           const float* __restrict__ Sr,
                                           ull (&acc)[4][4]) {
#pragma unroll 4
    for (int kl = 0; kl < CK_; kl++) {
        float4 w = wbuf[kl * H_ + jh];
        const float* row = Sr + kl * HSTRIDE_ + ROFF;
        ull wi = splat2(w.x), wf = splat2(w.y), wg = splat2(w.z), wo = splat2(w.w);
        if (NP == 4) {
            ulonglong2 q0 = *(const ulonglong2*)(row);
            ulonglong2 q1 = *(const ulonglong2*)(row + 4);
            acc[0][0] = ffma2(q0.x, wi, acc[0][0]);
            acc[1][0] = ffma2(q0.x, wf, acc[1][0]);
            acc[2][0] = ffma2(q0.x, wg, acc[2][0]);
            acc[3][0] = ffma2(q0.x, wo, acc[3][0]);
            acc[0][1] = ffma2(q0.y, wi, acc[0][1]);
            acc[1][1] = ffma2(q0.y, wf, acc[1][1]);
            acc[2][1] = ffma2(q0.y, wg, acc[2][1]);
            acc[3][1] = ffma2(q0.y, wo, acc[3][1]);
            acc[0][2] = ffma2(q1.x, wi, acc[0][2]);
            acc[1][2] = ffma2(q1.x, wf, acc[1][2]);
            acc[2][2] = ffma2(q1.x, wg, acc[2][2]);
            acc[3][2] = ffma2(q1.x, wo, acc[3][2]);
            acc[0][3] = ffma2(q1.y, wi, acc[0][3]);
            acc[1][3] = ffma2(q1.y, wf, acc[1][3]);
            acc[2][3] = ffma2(q1.y, wg, acc[2][3]);
            acc[3][3] = ffma2(q1.y, wo, acc[3][3]);
        } else {
            ulonglong2 q0 = *(const ulonglong2*)(row);
            ull h2 = *(const ull*)(row + 4);
            acc[0][0] = ffma2(q0.x, wi, acc[0][0]);
            acc[1][0] = ffma2(q0.x, wf, acc[1][0]);
            acc[2][0] = ffma2(q0.x, wg, acc[2][0]);
            acc[3][0] = ffma2(q0.x, wo, acc[3][0]);
            acc[0][1] = ffma2(q0.y, wi, acc[0][1]);
            acc[1][1] = ffma2(q0.y, wf, acc[1][1]);
            acc[2][1] = ffma2(q0.y, wg, acc[2][1]);
            acc[3][1] = ffma2(q0.y, wo, acc[3][1]);
            acc[0][2] = ffma2(h2, wi, acc[0][2]);
            acc[1][2] = ffma2(h2, wf, acc[1][2]);
            acc[2][2] = ffma2(h2, wg, acc[2][2]);
            acc[3][2] = ffma2(h2, wo, acc[3][2]);
        }
    }
}

// smem layout (float offsets):
#define SMF_BUF_  0                                      // 3 x 16384 floats
#define SMF_S_    (NBUF_ * CHUNK_FLOATS_)                // 49152
#define SMF_WFC_  (SMF_S_ + KTOT_ * HSTRIDE_)            // +5760
#define SMF_BFC_  (SMF_WFC_ + O_ * H_)                   // +1536
#define SMF_OS_   (SMF_BFC_ + 8)
#define SMF_RED_  (SMF_OS_ + MB_ * O_ + 4)
#define SMF_TOT_  (SMF_RED_ + MB_ * O_ * 4 + 4)
#define SMEM_BYTES_ (SMF_TOT_ * 4)

__global__ void __launch_bounds__(NTH_, 1)
lstm_kernel(const float* __restrict__ x, const float* __restrict__ Wfc,
            const float* __restrict__ bfc, float* __restrict__ out) {
    extern __shared__ __align__(16) float smem[];
    float* S    = smem + SMF_S_;
    float* WfcS = smem + SMF_WFC_;
    float* bfcS = smem + SMF_BFC_;
    float* oS   = smem + SMF_OS_;
    float* red  = smem + SMF_RED_;

    const unsigned smem_u32 = (unsigned)__cvta_generic_to_shared(smem);

    const int tid = threadIdx.x;
    const int jh  = tid & 255;
    const int wg  = tid >> 8;        // 0: pairs 0..3 (rows 0..7); 1: pairs 4..6 (rows 8..13)
    const int b0  = blockIdx.x * MB_;

    for (int i = tid; i < KTOT_ * HSTRIDE_; i += NTH_) S[i] = 0.0f;
    for (int i = tid; i < O_ * H_; i += NTH_) WfcS[i] = Wfc[i];
    if (tid < O_) bfcS[tid] = bfc[tid];

    float c[8];
#pragma unroll
    for (int r = 0; r < 8; r++) c[r] = 0.0f;

    const float4 bias = g_bias[jh];
    float* Hrow = S + (F_ + jh) * HSTRIDE_ + (wg ? 8 : 0);

    // ---- x stager lives in wg1: 224 slots ----
    const bool stager = (tid >= 256) && (tid < 256 + F_ * PAIRS_);
    int xf = 0, xp = 0;
    const float* xr0 = x;
    const float* xr1 = x;
    float xa = 0.0f, xb = 0.0f;
    if (stager) {
        int sid = tid - 256;
        xf = sid / PAIRS_;
        xp = sid - xf * PAIRS_;
        int r0 = b0 + 2 * xp;     if (r0 > B_ - 1) r0 = B_ - 1;
        int r1 = b0 + 2 * xp + 1; if (r1 > B_ - 1) r1 = B_ - 1;
        xr0 = x + (size_t)r0 * S_ * F_ + xf;
        xr1 = x + (size_t)r1 * S_ * F_ + xf;
        xa = xr0[0];
        xb = xr1[0];
    }

    // ---- weight pipeline prologue: chunks 0 and 1 in flight ----
    issue_chunk(smem_u32 + 0u * CHUNK_BYTES_, 0, tid);
    issue_chunk(smem_u32 + 1u * CHUNK_BYTES_, 1, tid);
    int m_issue = 2, b_issue = 2, b_comp = 0;

    __syncthreads();   // S init visible

    for (int t = 0; t < STEPS_; t++) {
        const bool la = (t >= WARM_);

        // ---- stage x_t into S rows 0..31 (la steps override f<6 with prev output) ----
        if (stager) {
            float v0 = xa, v1 = xb;
            if (la && xf < O_) {
                v0 = oS[(2 * xp) * O_ + xf];
                v1 = oS[(2 * xp + 1) * O_ + xf];
            }
            *(ull*)(S + xf * HSTRIDE_ + 2 * xp) = pk(v0, v1);
            int tn = t + 1;
            if (tn < STEPS_) {
                int tsn = (tn < WARM_) ? tn : (tn - WARM_);
                xa = xr0[(size_t)tsn * F_];
                xb = xr1[(size_t)tsn * F_];
            }
        }

        // ---- accumulators: low half starts from bias (proven fp order) ----
        ull acc[4][4], accS[4][4];
        {
            ull bi = splat2(bias.x), bf = splat2(bias.y),
                bg = splat2(bias.z), bo = splat2(bias.w);
#pragma unroll
            for (int p = 0; p < 4; p++) {
                acc[0][p] = bi; acc[1][p] = bf; acc[2][p] = bg; acc[3][p] = bo;
            }
        }
        const ull zero2 = splat2(0.0f);

        // ---- chunked GEMM: wait chunk, prefetch chunk+2, compute ----
        // Arithmetic replicates R4/R6 exactly:
        //   gates = (bias + sum k in [0,144)) + (sum k in [144,288))
#pragma unroll 1
        for (int mc = 0; mc < NCHUNK_; mc++) {
            CP_WAIT1();
            __syncthreads();   // chunk mc visible; orders x-stage & prev h-writes
            issue_chunk(smem_u32 + (unsigned)b_issue * CHUNK_BYTES_, m_issue, tid);
            if (++m_issue == NCHUNK_) m_issue = 0;
            if (++b_issue == NBUF_) b_issue = 0;
            const float4* wbuf = (const float4*)smem + (size_t)b_comp * (CK_ * H_);
            const float*  Sr   = S + mc * CK_ * HSTRIDE_;
            if (wg == 0) chunk_gemm<4, 0>(wbuf, jh, Sr, acc);
            else         chunk_gemm<3, 8>(wbuf, jh, Sr, acc);
            if (++b_comp == NBUF_) b_comp = 0;
            if (mc == SPLIT_CHUNK_) {    // k[0,144) complete: snapshot, restart at 0
#pragma unroll
                for (int g = 0; g < 4; g++)
#pragma unroll
                    for (int p = 0; p < 4; p++) { accS[g][p] = acc[g][p]; acc[g][p] = zero2; }
            }
        }
        __syncthreads();   // all S reads complete

        // ---- combine halves + elementwise LSTM cell + write own h floats ----
        {
            const int np = wg ? 3 : 4;
#pragma unroll
            for (int q = 0; q < 4; q++) {
                if (q >= np) break;
                float2 gi = unpk(add2(accS[0][q], acc[0][q]));
                float2 gf = unpk(add2(accS[1][q], acc[1][q]));
                float2 gg = unpk(add2(accS[2][q], acc[2][q]));
                float2 go = unpk(add2(accS[3][q], acc[3][q]));
                float c0 = sigf(gf.x) * c[2 * q]     + sigf(gi.x) * tanh_acc(gg.x);
                float c1 = sigf(gf.y) * c[2 * q + 1] + sigf(gi.y) * tanh_acc(gg.y);
                c[2 * q] = c0; c[2 * q + 1] = c1;
                *(ull*)(Hrow + 2 * q) = pk(sigf(go.x) * tanh_acc(c0),
                                           sigf(go.y) * tanh_acc(c1));
            }
        }

        // ---- STE readout: out = (h>0) @ W_fc^T + b_fc  (t = 95..127) ----
        if (t >= WARM_ - 1) {
            __syncthreads();   // h writes visible
            const float* Hs = S + F_ * HSTRIDE_;
            if (tid < MB_ * O_ * 4) {
                int slot  = tid >> 2;
                int chunk = tid & 3;
                int r  = slot / O_;
                int oi = slot - r * O_;
                const float* wrow = WfcS + oi * H_;
                float s0 = 0.0f, s1 = 0.0f;
                int jb = chunk * 64;
#pragma unroll 8
                for (int j = 0; j < 64; j += 2) {
                    s0 += (Hs[(jb + j) * HSTRIDE_ + r] > 0.0f)     ? wrow[jb + j]     : 0.0f;
                    s1 += (Hs[(jb + j + 1) * HSTRIDE_ + r] > 0.0f) ? wrow[jb + j + 1] : 0.0f;
                }
                red[slot * 4 + chunk] = s0 + s1;
            }
            __syncthreads();
            if (tid < MB_ * O_) {
                int r  = tid / O_;
                int oi = tid - r * O_;
                float a = bfcS[oi] + red[tid * 4 + 0] + red[tid * 4 + 1]
                                   + red[tid * 4 + 2] + red[tid * 4 + 3];
                oS[tid] = a;
                if (b0 + r < B_)
                    out[((size_t)(b0 + r) * (LA_ + 1) + (t - (WARM_ - 1))) * O_ + oi] = a;
            }
            __syncthreads();   // oS ready for next step's stager
        }
        // Non-readout steps: next iteration's first chunk barrier orders h-writes
        // before any h-row reads (chunks >= 2); x-stage writes touch only rows 0..31.
    }
}

extern "C" void kernel_launch(void* const* d_in, const int* in_sizes, int n_in,
                              void* d_out, int out_size) {
    const float* x    = (const float*)d_in[0];
    const float* W_ih = (const float*)d_in[1];
    const float* W_hh = (const float*)d_in[2];
    const float* b_ih = (const float*)d_in[3];
    const float* b_hh = (const float*)d_in[4];
    const float* W_fc = (const float*)d_in[5];
    const float* b_fc = (const float*)d_in[6];
    float* out = (float*)d_out;

    cudaFuncSetAttribute(lstm_kernel, cudaFuncAttributeMaxDynamicSharedMemorySize,
                         SMEM_BYTES_);

    pack_kernel<<<(KTOT_ * H_ + 255) / 256, 256>>>(W_ih, W_hh, b_ih, b_hh);
    lstm_kernel<<<NBLK_, NTH_, SMEM_BYTES_>>>(x, W_fc, b_fc, out);
}